// round 17
// baseline (speedup 1.0000x reference)
#include <cuda_runtime.h>
#include <math_constants.h>

#define BB 512
#define TT 512
#define KK 64

// 16.7 MB history scratch (argmax index per (b, t, j)), plus per-batch best-last tag.
__device__ unsigned char g_hist[(size_t)BB * TT * KK];
__device__ int g_best[BB];

// ---------------------------------------------------------------------------
// cp.async helpers (LDGSTS on sm_103): 16B global->shared, grouped.
// ---------------------------------------------------------------------------
__device__ __forceinline__ void cp_async16(void* smem_dst, const void* gsrc) {
    unsigned saddr = (unsigned)__cvta_generic_to_shared(smem_dst);
    asm volatile("cp.async.ca.shared.global [%0], [%1], 16;"
                 :: "r"(saddr), "l"(gsrc));
}
__device__ __forceinline__ void cp_commit() {
    asm volatile("cp.async.commit_group;");
}
__device__ __forceinline__ void cp_wait1() {
    asm volatile("cp.async.wait_group 1;");
}

// ---------------------------------------------------------------------------
// Order-preserving monotonic float->u32 key (total order on non-NaN floats).
// ---------------------------------------------------------------------------
__device__ __forceinline__ unsigned fkey(float v) {
    const int i = __float_as_int(v);
    return (i >= 0) ? ((unsigned)i | 0x80000000u) : (unsigned)(~i);
}

// Warp-wide max of keys in ONE instruction (sm_80+: redux.sync.max.u32).
__device__ __forceinline__ unsigned warp_max_key(unsigned key) {
    unsigned r;
    asm("redux.sync.max.u32 %0, %1, 0xffffffff;" : "=r"(r) : "r"(key));
    return r;
}

// ---------------------------------------------------------------------------
// Forward Viterbi: one WARP per batch, 4 warps/block sharing the trans tile.
// Lane l owns next-tags j0=l, j1=l+32.  (Structure = R14 winner; changes:
// dual compare-select chains in phase A + key-space threshold compare.)
//   - emissions via double-buffered cp.async tiles (8 steps/tile), issued 8
//     steps ahead -> DRAM latency off the per-step chain.
//   - threshold: keep i iff s_i >= smax + thrD  <=>  s_i + negD >= smax
//     (negD = (Tmax - Tmin) + 0.05). Implemented in key space:
//     fkey(s + negD) >= kmax, with kmax = redux(fkey(max(s0,s1))); the
//     per-lane keys are computed in PARALLEL with the redux. The <=1ulp
//     rounding of fl(s + negD) is absorbed by the 0.05 margin -> the kept
//     set remains a superset of any possible argmax => pruning exact.
//     (R16 bug: the test was inverted as fkey(s - negD) >= kmax -> empty
//      live set -> garbage. Corrected here.)
//   - live prev-tag set: compacted ASCENDING index list in shared (int4
//     groups, sentinel idx=64 with score -inf / trans 0), from two ballots.
//   - argmax: TWO strict-'>' chains (group positions x,z / y,w, each
//     ascending) merged with (greater value | equal value -> smaller index)
//     -> exact jnp.argmax first-occurrence semantics.
// ---------------------------------------------------------------------------
__global__ __launch_bounds__(128) void viterbi_forward(
    const float* __restrict__ emissions,   // [B, T, K]
    const int*   __restrict__ mask,        // [B, T]
    const float* __restrict__ start_t,     // [K]
    const float* __restrict__ end_t,       // [K]
    const float* __restrict__ trans)       // [K, K]
{
    const int tid  = threadIdx.x;
    const int lane = tid & 31;
    const int w    = tid >> 5;
    const int b    = blockIdx.x * 4 + w;

    __shared__ __align__(16) float2 tp_sh[KK + 1][32];      // row 64 = zeros
    __shared__ __align__(16) float  score_sh[4][2][72];     // [64] = -inf
    __shared__ __align__(16) int    live_sh[4][2][72];      // ascending + pads
    __shared__ __align__(16) float  em_sh[4][2][8 * KK];    // emission tiles
    __shared__ int   smask_sh[4][TT];
    __shared__ float red_sh[8];

    const float* em = emissions + (size_t)b * TT * KK;
    const int*   mk = mask + (size_t)b * TT;

    // ---- issue first two emission tiles immediately ----
    {
        float* dst0 = &em_sh[w][0][0];
        const float* src0 = em;                  // steps [0,8)
#pragma unroll
        for (int k = 0; k < 4; ++k)
            cp_async16(dst0 + k * 128 + lane * 4, src0 + k * 128 + lane * 4);
        cp_commit();
        float* dst1 = &em_sh[w][1][0];
        const float* src1 = em + 8 * KK;         // steps [8,16)
#pragma unroll
        for (int k = 0; k < 4; ++k)
            cp_async16(dst1 + k * 128 + lane * 4, src1 + k * 128 + lane * 4);
        cp_commit();
    }

    // ---- one-time: stage trans (pair layout) + mask row, global Tmin/Tmax ----
    float tmn = CUDART_INF_F, tmx = -CUDART_INF_F;
    for (int i = w; i < KK; i += 4) {
        const float a = trans[i * KK + lane];
        const float c = trans[i * KK + 32 + lane];
        tp_sh[i][lane] = make_float2(a, c);
        tmn = fminf(tmn, fminf(a, c));
        tmx = fmaxf(tmx, fmaxf(a, c));
    }
    if (w == 0) tp_sh[KK][lane] = make_float2(0.0f, 0.0f);   // sentinel row
    if (lane == 0) {
        score_sh[w][0][KK] = -CUDART_INF_F;                  // sentinel scores
        score_sh[w][1][KK] = -CUDART_INF_F;
    }
    for (int k = lane; k < TT; k += 32) smask_sh[w][k] = mk[k];
#pragma unroll
    for (int d = 16; d; d >>= 1) {
        tmn = fminf(tmn, __shfl_xor_sync(0xFFFFFFFFu, tmn, d));
        tmx = fmaxf(tmx, __shfl_xor_sync(0xFFFFFFFFu, tmx, d));
    }
    if (lane == 0) { red_sh[w] = tmn; red_sh[4 + w] = tmx; }
    __syncthreads();                                          // last block sync
    const float mn = fminf(fminf(red_sh[0], red_sh[1]), fminf(red_sh[2], red_sh[3]));
    const float mx = fmaxf(fmaxf(red_sh[4], red_sh[5]), fmaxf(red_sh[6], red_sh[7]));
    // keep i iff s_i + negD >= smax  (equivalent to s_i >= smax + thrD)
    const float negD = (mx - mn) + 0.05f;

    const unsigned lanemask = (1u << lane) - 1u;

    // ---- tile 0 ready ----
    cp_wait1();
    __syncwarp();
    int ebuf = 0;

    // ---- init scores (t = 0) + initial live list into buffer 0 ----
    float s0 = start_t[lane]      + em_sh[w][0][lane];
    float s1 = start_t[lane + 32] + em_sh[w][0][32 + lane];
    int nl;
    {
        const unsigned kmax = warp_max_key(fkey(fmaxf(s0, s1)));
        const unsigned k0 = fkey(s0 + negD);
        const unsigned k1 = fkey(s1 + negD);
        const unsigned b0 = __ballot_sync(0xFFFFFFFFu, k0 >= kmax);
        const unsigned b1 = __ballot_sync(0xFFFFFFFFu, k1 >= kmax);
        nl = __popc(b0) + __popc(b1);
        score_sh[w][0][lane]      = s0;
        score_sh[w][0][lane + 32] = s1;
        if ((b0 >> lane) & 1u)
            live_sh[w][0][__popc(b0 & lanemask)] = lane;
        if ((b1 >> lane) & 1u)
            live_sh[w][0][__popc(b0) + __popc(b1 & lanemask)] = lane + 32;
        if (lane < 4) live_sh[w][0][nl + lane] = KK;          // sentinel pads
        __syncwarp();
    }

    // ---- e / mask for t = 1 (from shared) ----
    float e0c = em_sh[w][0][KK + lane];
    float e1c = em_sh[w][0][KK + 32 + lane];
    int   mc  = smask_sh[w][1];

    unsigned char* hp = g_hist + ((size_t)b * TT + 1) * KK;

    int p = 0;
    for (int t = 1; t < TT; ++t) {
        // ---- tile boundary: t+1 enters a new 8-step tile ----
        if ((t & 7) == 7) {
            const int nbase = (t + 9 <= TT - 8) ? (t + 9) : (TT - 8);
            float* dst = &em_sh[w][ebuf][0];     // vacated buffer
            const float* src = em + (size_t)nbase * KK;
#pragma unroll
            for (int k = 0; k < 4; ++k)
                cp_async16(dst + k * 128 + lane * 4, src + k * 128 + lane * 4);
            cp_commit();
            cp_wait1();                          // tile containing t+1 complete
            __syncwarp();
            ebuf ^= 1;
        }

        // ---- phase A: argmax over compacted live list, DUAL chains ----
        // chain A takes group positions x,z; chain B takes y,w. Each chain
        // scans ascending indices with strict '>'; exact merge below.
        const float* sc = score_sh[w][p];
        const int4*  lv = (const int4*)live_sh[w][p];
        const int ng = (nl + 3) >> 2;

        float bA0 = -CUDART_INF_F, bB0 = -CUDART_INF_F;
        float bA1 = -CUDART_INF_F, bB1 = -CUDART_INF_F;
        int   iA0 = 0, iB0 = 0, iA1 = 0, iB1 = 0;
        for (int g = 0; g < ng; ++g) {
            const int4 iv = lv[g];
            const float  sa = sc[iv.x], sb = sc[iv.y];
            const float  scq = sc[iv.z], sd = sc[iv.w];
            const float2 ta = tp_sh[iv.x][lane];
            const float2 tb = tp_sh[iv.y][lane];
            const float2 tc = tp_sh[iv.z][lane];
            const float2 td = tp_sh[iv.w][lane];
            const float va0 = (sa + ta.x) + e0c, va1 = (sa + ta.y) + e1c;
            const float vb0 = (sb + tb.x) + e0c, vb1 = (sb + tb.y) + e1c;
            const float vc0 = (scq + tc.x) + e0c, vc1 = (scq + tc.y) + e1c;
            const float vd0 = (sd + td.x) + e0c, vd1 = (sd + td.y) + e1c;
            // chain A: x then z
            { const bool g0 = va0 > bA0; bA0 = g0 ? va0 : bA0; iA0 = g0 ? iv.x : iA0;
              const bool g1 = va1 > bA1; bA1 = g1 ? va1 : bA1; iA1 = g1 ? iv.x : iA1; }
            { const bool g0 = vc0 > bA0; bA0 = g0 ? vc0 : bA0; iA0 = g0 ? iv.z : iA0;
              const bool g1 = vc1 > bA1; bA1 = g1 ? vc1 : bA1; iA1 = g1 ? iv.z : iA1; }
            // chain B: y then w (independent of chain A -> runs in parallel)
            { const bool g0 = vb0 > bB0; bB0 = g0 ? vb0 : bB0; iB0 = g0 ? iv.y : iB0;
              const bool g1 = vb1 > bB1; bB1 = g1 ? vb1 : bB1; iB1 = g1 ? iv.y : iB1; }
            { const bool g0 = vd0 > bB0; bB0 = g0 ? vd0 : bB0; iB0 = g0 ? iv.w : iB0;
              const bool g1 = vd1 > bB1; bB1 = g1 ? vd1 : bB1; iB1 = g1 ? iv.w : iB1; }
        }
        // exact merge: greater value wins; equal values -> smaller index.
        const bool m0 = (bB0 > bA0) || ((bB0 == bA0) && (iB0 < iA0));
        const float bst0 = m0 ? bB0 : bA0;
        const int   bid0 = m0 ? iB0 : iA0;
        const bool m1 = (bB1 > bA1) || ((bB1 == bA1) && (iB1 < iA1));
        const float bst1 = m1 ? bB1 : bA1;
        const int   bid1 = m1 ? iB1 : iA1;

        // history always records the argmax; mask only gates the score.
        hp[lane]      = (unsigned char)bid0;
        hp[lane + 32] = (unsigned char)bid1;

        s0 = mc ? bst0 : s0;
        s1 = mc ? bst1 : s1;

        // ---- threshold in KEY space: per-lane keys overlap the redux ----
        const unsigned kmax = warp_max_key(fkey(fmaxf(s0, s1)));
        const unsigned k0 = fkey(s0 + negD);     // independent of redux
        const unsigned k1 = fkey(s1 + negD);
        const unsigned bb0 = __ballot_sync(0xFFFFFFFFu, k0 >= kmax);
        const unsigned bb1 = __ballot_sync(0xFFFFFFFFu, k1 >= kmax);
        nl = __popc(bb0) + __popc(bb1);

        const int q = p ^ 1;
        score_sh[w][q][lane]      = s0;
        score_sh[w][q][lane + 32] = s1;
        if ((bb0 >> lane) & 1u)
            live_sh[w][q][__popc(bb0 & lanemask)] = lane;
        if ((bb1 >> lane) & 1u)
            live_sh[w][q][__popc(bb0) + __popc(bb1 & lanemask)] = lane + 32;
        if (lane < 4) live_sh[w][q][nl + lane] = KK;          // sentinel pads
        __syncwarp();

        // ---- prefetch e / mask for t+1 from shared (overlaps next phase A) ----
        const int tn  = (t + 1 < TT) ? (t + 1) : (TT - 1);
        const int off = (tn & 7) * KK;
        e0c = em_sh[w][ebuf][off + lane];
        e1c = em_sh[w][ebuf][off + 32 + lane];
        mc  = smask_sh[w][tn];

        p = q;
        hp += KK;
    }

    // ---- final: + end_transitions, first-index argmax over all 64 tags ----
    {
        const float v0 = s0 + end_t[lane];
        const float v1 = s1 + end_t[lane + 32];
        float bv; int bi;
        if (v1 > v0) { bv = v1; bi = lane + 32; }
        else         { bv = v0; bi = lane; }
#pragma unroll
        for (int d = 16; d; d >>= 1) {
            const float vo = __shfl_xor_sync(0xFFFFFFFFu, bv, d);
            const int   io = __shfl_xor_sync(0xFFFFFFFFu, bi, d);
            if (vo > bv || (vo == bv && io < bi)) { bv = vo; bi = io; }
        }
        if (lane == 0) g_best[b] = bi;
    }
}

// ---------------------------------------------------------------------------
// Backtrace: one block per batch. Stage the 32KB history slab + mask into
// shared, then one thread walks the dependent chain at LDS latency.
// Output tags written as FLOAT32 (harness output dtype).
// ---------------------------------------------------------------------------
__global__ __launch_bounds__(256) void viterbi_backtrace(
    const int*  __restrict__ mask,   // [B, T]
    float*      __restrict__ out)    // [B, T] float32 tags
{
    const int b = blockIdx.x;
    __shared__ unsigned char h[TT * KK];   // 32 KB
    __shared__ int msk[TT];                // 2 KB

    const uint4* src = (const uint4*)(g_hist + (size_t)b * TT * KK);
    uint4* dst = (uint4*)h;
#pragma unroll 4
    for (int k = threadIdx.x; k < (TT * KK) / 16; k += blockDim.x)
        dst[k] = src[k];
    for (int t = threadIdx.x; t < TT; t += blockDim.x)
        msk[t] = mask[b * TT + t];
    __syncthreads();

    if (threadIdx.x == 0) {
        int tag = g_best[b];
        out[b * TT + (TT - 1)] = (float)tag;
        for (int t = TT - 1; t >= 1; --t) {
            const int prev = h[t * KK + tag];
            tag = msk[t] ? prev : tag;
            out[b * TT + t - 1] = (float)tag;
        }
    }
}

extern "C" void kernel_launch(void* const* d_in, const int* in_sizes, int n_in,
                              void* d_out, int out_size)
{
    // Bind inputs by element count:
    //   16777216 -> emissions, 262144 -> attn_mask, 4096 -> transitions,
    //   64 -> start_transitions (first), end_transitions (second)
    const float* emissions = nullptr;
    const int*   attn_mask = nullptr;
    const float* start_t   = nullptr;
    const float* end_t     = nullptr;
    const float* trans     = nullptr;

    for (int i = 0; i < n_in; ++i) {
        const int sz = in_sizes[i];
        if (sz == BB * TT * KK)      emissions = (const float*)d_in[i];
        else if (sz == BB * TT)      attn_mask = (const int*)d_in[i];
        else if (sz == KK * KK)      trans     = (const float*)d_in[i];
        else if (sz == KK) {
            if (!start_t) start_t = (const float*)d_in[i];
            else          end_t   = (const float*)d_in[i];
        }
    }

    float* out = (float*)d_out;  // [512,512] float32 tag values

    viterbi_forward<<<BB / 4, 128>>>(emissions, attn_mask, start_t, end_t, trans);
    viterbi_backtrace<<<BB, 256>>>(attn_mask, out);
}